// round 1
// baseline (speedup 1.0000x reference)
#include <cuda_runtime.h>
#include <cstdint>

// COO SpMM: C[row[e], :] += edata[e] * B[col[e], :],  H = 64.
// Inputs (metadata order): edata f32[NNZ], row i32[NNZ], col i32[NNZ], B f32[N_COLS*64]
// Output: C f32[100000*64]
//
// Strategy: 16 threads per edge; each thread owns one float4 (4 of the 64
// columns). Gather B row (256B contiguous per 16-lane group, L2-resident)
// and scatter with vector red.global.add.v4.f32 (sm_90+), which cuts the
// atomic-op count 4x vs scalar atomicAdd.

__global__ void zero_out_kernel(float4* __restrict__ out, int n4) {
    int i = blockIdx.x * blockDim.x + threadIdx.x;
    int stride = gridDim.x * blockDim.x;
    for (; i < n4; i += stride)
        out[i] = make_float4(0.f, 0.f, 0.f, 0.f);
}

__global__ void __launch_bounds__(256)
spmm_coo_v4red_kernel(const float* __restrict__ edata,
                      const int*   __restrict__ row,
                      const int*   __restrict__ col,
                      const float4* __restrict__ B4,
                      float4* __restrict__ C4,
                      int nnz) {
    // 16 threads per edge
    unsigned int t = blockIdx.x * blockDim.x + threadIdx.x;
    int e = (int)(t >> 4);
    int j = (int)(t & 15);
    if (e >= nnz) return;

    float w = __ldg(edata + e);       // 16-way broadcast, L1-served
    int   c = __ldg(col + e);
    int   r = __ldg(row + e);

    float4 b = __ldg(B4 + (size_t)c * 16 + j);   // coalesced 256B per group, L2 hit

    float vx = w * b.x;
    float vy = w * b.y;
    float vz = w * b.z;
    float vw = w * b.w;

    float4* dst = C4 + (size_t)r * 16 + j;
    asm volatile("red.global.add.v4.f32 [%0], {%1, %2, %3, %4};"
                 :: "l"(dst), "f"(vx), "f"(vy), "f"(vz), "f"(vw)
                 : "memory");
}

extern "C" void kernel_launch(void* const* d_in, const int* in_sizes, int n_in,
                              void* d_out, int out_size) {
    const float* edata = (const float*)d_in[0];
    const int*   row   = (const int*)d_in[1];
    const int*   col   = (const int*)d_in[2];
    const float4* B4   = (const float4*)d_in[3];
    float4* C4 = (float4*)d_out;

    int nnz = in_sizes[0];

    // Zero output (poisoned to 0xAA by harness). out_size is in f32 elements.
    int n4 = out_size / 4;
    {
        int threads = 256;
        int blocks = (n4 + threads - 1) / threads;
        if (blocks > 8192) blocks = 8192;
        zero_out_kernel<<<blocks, threads>>>(C4, n4);
    }

    // Scatter SpMM: nnz * 16 threads total.
    {
        int threads = 256;
        long long total = (long long)nnz * 16;
        int blocks = (int)((total + threads - 1) / threads);
        spmm_coo_v4red_kernel<<<blocks, threads>>>(edata, row, col, B4, C4, nnz);
    }
}

// round 2
// speedup vs baseline: 1.3719x; 1.3719x over previous
#include <cuda_runtime.h>
#include <cstdint>

// COO SpMM: C[row[e], :] += edata[e] * B[col[e], :],  H = 64.
// Two-phase: COO -> row-sorted (val,col) pairs (histogram + scan + scatter),
// then gather-only CSR SpMM with register accumulation (no atomics on C).
//
// Inputs: edata f32[NNZ], row i32[NNZ], col i32[NNZ], B f32[N_COLS*64]
// Output: C f32[N_ROWS*64]

#define MAX_NNZ   3400000
#define MAX_ROWS  131072
#define SCAN_BLK  1024

__device__ int    g_cnt[MAX_ROWS];
__device__ int    g_off[MAX_ROWS];
__device__ int    g_cur[MAX_ROWS];
__device__ int    g_bsum[MAX_ROWS / SCAN_BLK + 2];
__device__ float2 g_pairs[MAX_NNZ];

// ---------------------------------------------------------------- phase A
__global__ void zero_cnt_kernel(int n_rows) {
    int i = blockIdx.x * blockDim.x + threadIdx.x;
    if (i < n_rows) g_cnt[i] = 0;
}

__global__ void hist_kernel(const int* __restrict__ row, int nnz) {
    int e = blockIdx.x * blockDim.x + threadIdx.x;
    if (e < nnz) atomicAdd(&g_cnt[row[e]], 1);
}

// Block-level exclusive scan of g_cnt -> g_off (partial), block totals -> g_bsum
__global__ void scan1_kernel(int n_rows) {
    __shared__ int s[SCAN_BLK];
    int tid = threadIdx.x;
    int i = blockIdx.x * SCAN_BLK + tid;
    int v = (i < n_rows) ? g_cnt[i] : 0;
    s[tid] = v;
    __syncthreads();
    for (int d = 1; d < SCAN_BLK; d <<= 1) {
        int t = (tid >= d) ? s[tid - d] : 0;
        __syncthreads();
        s[tid] += t;
        __syncthreads();
    }
    if (i < n_rows) g_off[i] = s[tid] - v;   // exclusive
    if (tid == SCAN_BLK - 1) g_bsum[blockIdx.x] = s[tid];
}

// Single-block exclusive scan of the block sums (nb <= 128)
__global__ void scan2_kernel(int nb) {
    __shared__ int s[128];
    int tid = threadIdx.x;
    int v = (tid < nb) ? g_bsum[tid] : 0;
    s[tid] = v;
    __syncthreads();
    for (int d = 1; d < 128; d <<= 1) {
        int t = (tid >= d) ? s[tid - d] : 0;
        __syncthreads();
        s[tid] += t;
        __syncthreads();
    }
    if (tid < nb) g_bsum[tid] = s[tid] - v;  // exclusive
}

// Apply block offsets; init scatter cursors
__global__ void scan3_kernel(int n_rows) {
    int i = blockIdx.x * blockDim.x + threadIdx.x;
    if (i < n_rows) {
        int o = g_off[i] + g_bsum[i / SCAN_BLK];
        g_off[i] = o;
        g_cur[i] = o;
    }
}

// Scatter edges into row-sorted (val, col) pairs
__global__ void scatter_kernel(const float* __restrict__ edata,
                               const int*   __restrict__ row,
                               const int*   __restrict__ col,
                               int nnz) {
    int e = blockIdx.x * blockDim.x + threadIdx.x;
    if (e >= nnz) return;
    int r = row[e];
    int pos = atomicAdd(&g_cur[r], 1);
    g_pairs[pos] = make_float2(edata[e], __int_as_float(col[e]));
}

// ---------------------------------------------------------------- phase B
// Gather-only CSR SpMM. 16 threads per row; lane j owns float4 j of H=64.
// Unroll x4 -> 4 independent L2 gathers in flight per lane.
__global__ void __launch_bounds__(256)
csr_spmm_kernel(const float4* __restrict__ B4,
                float4* __restrict__ C4,
                int n_rows) {
    unsigned int t = blockIdx.x * blockDim.x + threadIdx.x;
    int r = (int)(t >> 4);
    int j = (int)(t & 15);
    if (r >= n_rows) return;

    int start = g_off[r];
    int m     = g_cnt[r];

    float4 acc = make_float4(0.f, 0.f, 0.f, 0.f);

    int i = 0;
    for (; i + 4 <= m; i += 4) {
        float2 p0 = __ldg(&g_pairs[start + i]);
        float2 p1 = __ldg(&g_pairs[start + i + 1]);
        float2 p2 = __ldg(&g_pairs[start + i + 2]);
        float2 p3 = __ldg(&g_pairs[start + i + 3]);
        float4 b0 = __ldg(B4 + (size_t)__float_as_int(p0.y) * 16 + j);
        float4 b1 = __ldg(B4 + (size_t)__float_as_int(p1.y) * 16 + j);
        float4 b2 = __ldg(B4 + (size_t)__float_as_int(p2.y) * 16 + j);
        float4 b3 = __ldg(B4 + (size_t)__float_as_int(p3.y) * 16 + j);
        acc.x += p0.x * b0.x; acc.y += p0.x * b0.y; acc.z += p0.x * b0.z; acc.w += p0.x * b0.w;
        acc.x += p1.x * b1.x; acc.y += p1.x * b1.y; acc.z += p1.x * b1.z; acc.w += p1.x * b1.w;
        acc.x += p2.x * b2.x; acc.y += p2.x * b2.y; acc.z += p2.x * b2.z; acc.w += p2.x * b2.w;
        acc.x += p3.x * b3.x; acc.y += p3.x * b3.y; acc.z += p3.x * b3.z; acc.w += p3.x * b3.w;
    }
    for (; i < m; i++) {
        float2 p = __ldg(&g_pairs[start + i]);
        float4 b = __ldg(B4 + (size_t)__float_as_int(p.y) * 16 + j);
        acc.x += p.x * b.x; acc.y += p.x * b.y; acc.z += p.x * b.z; acc.w += p.x * b.w;
    }

    // Single write; also zeroes empty rows (output is poison-initialized).
    C4[(size_t)r * 16 + j] = acc;
}

// ---------------------------------------------------------------- launch
extern "C" void kernel_launch(void* const* d_in, const int* in_sizes, int n_in,
                              void* d_out, int out_size) {
    const float* edata = (const float*)d_in[0];
    const int*   row   = (const int*)d_in[1];
    const int*   col   = (const int*)d_in[2];
    const float4* B4   = (const float4*)d_in[3];
    float4* C4 = (float4*)d_out;

    int nnz    = in_sizes[0];
    int n_rows = out_size / 64;                 // H = 64
    int nb     = (n_rows + SCAN_BLK - 1) / SCAN_BLK;

    zero_cnt_kernel<<<(n_rows + 255) / 256, 256>>>(n_rows);
    hist_kernel<<<(nnz + 255) / 256, 256>>>(row, nnz);
    scan1_kernel<<<nb, SCAN_BLK>>>(n_rows);
    scan2_kernel<<<1, 128>>>(nb);
    scan3_kernel<<<(n_rows + 255) / 256, 256>>>(n_rows);
    scatter_kernel<<<(nnz + 255) / 256, 256>>>(edata, row, col, nnz);

    long long total = (long long)n_rows * 16;
    csr_spmm_kernel<<<(int)((total + 255) / 256), 256>>>(B4, C4, n_rows);
}